// round 5
// baseline (speedup 1.0000x reference)
#include <cuda_runtime.h>
#include <cstdint>

#define Bsz     32768
#define Dd      1024
#define Cc      40
#define CT      80            // 40 fwd + 40 rev output columns
#define RB      64            // rows (M) per CTA -> 512 CTAs
#define THREADS 128           // 4 warps: 2 M-warps x 2 N-warps, each 2 m-tiles x 5 n-tiles
#define KC      32            // k per chunk -> 128B rows, XOR swizzle (no pad)
#define NCH     (Dd / KC)     // 32
#define NSTAGE  3

#define A_FLOATS   (RB * KC)              // 2048
#define B_FLOATS   (CT * KC)              // 2560
#define STAGE_F    (A_FLOATS + B_FLOATS)  // 4608 floats = 18432 B
#define OFF0_F     256                    // 1024 B front
#define SMEM_BYTES ((OFF0_F + NSTAGE * STAGE_F) * 4)   // 56320 B -> 4 CTAs/SM

// epilogue overlay (aliases stage buffers after mainloop)
#define BROW    81
#define EPI_BASE_F  OFF0_F
#define EPI_WT_F    (EPI_BASE_F + RB * BROW)          // bases 64x81 = 5184
#define EPI_BB_F    (EPI_WT_F + 2 * Cc * Cc)

#define SWZ(b) ((b) ^ ((((unsigned)(b)) >> 3) & 0x70u))

extern __shared__ float smf[];

__device__ __forceinline__ uint32_t tf32(float x) {
    uint32_t r;
    asm("cvt.rna.tf32.f32 %0, %1;" : "=r"(r) : "f"(x));
    return r;
}

__device__ __forceinline__ void mma_16x8x8(float* d, const uint32_t* a,
                                           const uint32_t* bfr) {
    asm volatile(
        "mma.sync.aligned.m16n8k8.row.col.f32.tf32.tf32.f32 "
        "{%0,%1,%2,%3}, {%4,%5,%6,%7}, {%8,%9}, {%0,%1,%2,%3};"
        : "+f"(d[0]), "+f"(d[1]), "+f"(d[2]), "+f"(d[3])
        : "r"(a[0]), "r"(a[1]), "r"(a[2]), "r"(a[3]), "r"(bfr[0]), "r"(bfr[1]));
}

__global__ void __launch_bounds__(THREADS, 4)
bichain_mma5(const float* __restrict__ src,
             const float* __restrict__ W,  const float* __restrict__ b,
             const float* __restrict__ Wr, const float* __restrict__ br,
             float* __restrict__ out) {
    const int tid  = threadIdx.x;
    const int warp = tid >> 5;
    const int lane = tid & 31;
    const int row0 = blockIdx.x * RB;

    uint32_t smb;
    asm("{ .reg .u64 t; cvta.to.shared.u64 t, %1; cvt.u32.u64 %0, t; }"
        : "=r"(smb) : "l"(smf));

    // ---- per-thread cp.async source pointers (advance by KC per chunk) ----
    const int r8  = tid >> 3;          // 0..15
    const int seg = tid & 7;           // 0..7 (16B segments)
    const float* gA = src + (size_t)(row0 + r8) * Dd + seg * 4;
    const float* gB[5];
    #pragma unroll
    for (int i = 0; i < 5; ++i) {
        const int rb = r8 + 16 * i;    // 0..79
        gB[i] = (rb < Cc ? W  + (size_t)rb        * (Dd + Cc)
                         : Wr + (size_t)(rb - Cc) * (Dd + Cc)) + seg * 4;
    }
    // swizzled destination offsets are chunk-invariant
    uint32_t dA[4], dB[5];
    #pragma unroll
    for (int i = 0; i < 4; ++i) dA[i] = SWZ((r8 + 16 * i) * 128 + seg * 16);
    #pragma unroll
    for (int i = 0; i < 5; ++i) dB[i] = SWZ((r8 + 16 * i) * 128 + seg * 16);

    auto issue = [&](int ch) {
        const uint32_t sA = smb + (OFF0_F + (ch % NSTAGE) * STAGE_F) * 4;
        const uint32_t sB = sA + A_FLOATS * 4;
        #pragma unroll
        for (int i = 0; i < 4; ++i) {                 // A: 64 rows x 8 segs (streaming)
            const float* g = gA + (size_t)(16 * i) * Dd;
            asm volatile("cp.async.cg.shared.global [%0], [%1], 16;"
                         :: "r"(sA + dA[i]), "l"(g));
        }
        #pragma unroll
        for (int i = 0; i < 5; ++i)                   // B: 80 rows x 8 segs (L1-reused)
            asm volatile("cp.async.ca.shared.global [%0], [%1], 16;"
                         :: "r"(sB + dB[i]), "l"(gB[i]));
        asm volatile("cp.async.commit_group;");
        gA += KC;
        #pragma unroll
        for (int i = 0; i < 5; ++i) gB[i] += KC;
    };

    // warp tiling: 2 M-warps (32 rows) x 2 N-warps (40 cols); 2 m-tiles x 5 n-tiles
    const int mw = warp >> 1;
    const int nw = warp & 1;
    const int qr = lane >> 2;
    const int qc = lane & 3;

    // per-row swizzle state: float base index and xor key
    int baA[2][2], xA[2][2];           // [mt][0]=row, [1]=row+8
    #pragma unroll
    for (int mt = 0; mt < 2; ++mt) {
        const int r0r = mw * 32 + mt * 16 + qr;
        baA[mt][0] = r0r * KC;        xA[mt][0] = r0r & 7;
        baA[mt][1] = (r0r + 8) * KC;  xA[mt][1] = (r0r + 8) & 7;
    }
    int baB[5], xB[5];
    #pragma unroll
    for (int t = 0; t < 5; ++t) {
        const int n = nw * 40 + t * 8 + qr;
        baB[t] = n * KC;  xB[t] = n & 7;
    }

    float acc[2][5][4];
    #pragma unroll
    for (int mt = 0; mt < 2; ++mt)
        #pragma unroll
        for (int t = 0; t < 5; ++t)
            #pragma unroll
            for (int e = 0; e < 4; ++e) acc[mt][t][e] = 0.f;

    issue(0); issue(1);

    for (int ch = 0; ch < NCH; ++ch) {
        if (ch < NCH - 1) asm volatile("cp.async.wait_group 1;");
        else              asm volatile("cp.async.wait_group 0;");
        __syncthreads();
        if (ch + 2 < NCH) issue(ch + 2);              // writes stage (ch-1)%3: safe

        const float* Ap = smf + OFF0_F + (ch % NSTAGE) * STAGE_F;
        const float* Bp = Ap + A_FLOATS;

        #pragma unroll
        for (int kk = 0; kk < KC / 8; ++kk) {
            const int c0 = kk * 2;                    // 16B-chunk index of k-group
            uint32_t afr[2][4], bfr[5][2];
            #pragma unroll
            for (int mt = 0; mt < 2; ++mt) {
                afr[mt][0] = tf32(Ap[baA[mt][0] + (((c0    ) ^ xA[mt][0]) << 2) + qc]);
                afr[mt][1] = tf32(Ap[baA[mt][1] + (((c0    ) ^ xA[mt][1]) << 2) + qc]);
                afr[mt][2] = tf32(Ap[baA[mt][0] + (((c0 + 1) ^ xA[mt][0]) << 2) + qc]);
                afr[mt][3] = tf32(Ap[baA[mt][1] + (((c0 + 1) ^ xA[mt][1]) << 2) + qc]);
            }
            #pragma unroll
            for (int t = 0; t < 5; ++t) {
                bfr[t][0] = tf32(Bp[baB[t] + (((c0    ) ^ xB[t]) << 2) + qc]);
                bfr[t][1] = tf32(Bp[baB[t] + (((c0 + 1) ^ xB[t]) << 2) + qc]);
            }
            #pragma unroll
            for (int mt = 0; mt < 2; ++mt)
                #pragma unroll
                for (int t = 0; t < 5; ++t)
                    mma_16x8x8(acc[mt][t], afr[mt], bfr[t]);
        }
    }
    __syncthreads();   // all warps done reading stages before overlay writes

    // ---- accumulators -> smem bases[64][81] ----
    float* bases = smf + EPI_BASE_F;
    #pragma unroll
    for (int mt = 0; mt < 2; ++mt) {
        const int r = mw * 32 + mt * 16 + qr;
        #pragma unroll
        for (int t = 0; t < 5; ++t) {
            const int c = nw * 40 + t * 8 + qc * 2;
            bases[(r    ) * BROW + c    ] = acc[mt][t][0];
            bases[(r    ) * BROW + c + 1] = acc[mt][t][1];
            bases[(r + 8) * BROW + c    ] = acc[mt][t][2];
            bases[(r + 8) * BROW + c + 1] = acc[mt][t][3];
        }
    }

    // chain tail weights W[:,1024:1064] + biases
    float* wt = smf + EPI_WT_F;
    float* bb = smf + EPI_BB_F;
    for (int idx = tid; idx < 2 * Cc * Cc; idx += THREADS) {
        const int chn = idx / (Cc * Cc);
        const int rem = idx - chn * Cc * Cc;
        const int i = rem / Cc, j = rem % Cc;
        const float* Wp = chn ? Wr : W;
        wt[idx] = Wp[(size_t)i * (Dd + Cc) + Dd + j];
    }
    if (tid < 2 * Cc) bb[tid] = (tid < Cc) ? b[tid] : br[tid - Cc];
    __syncthreads();

    // ---- sequential chains: 128 threads = 64 rows x 2 chains ----
    {
        const int row = tid >> 1, chn = tid & 1;
        float* my        = bases + row * BROW + chn * Cc;
        const float* wtc = wt + chn * Cc * Cc;
        const float* bbc = bb + chn * Cc;
        float s[Cc];
        #pragma unroll
        for (int i = 0; i < Cc; ++i) {
            float x = my[i] + bbc[i];
            #pragma unroll
            for (int j = 0; j < i; ++j)
                x = fmaf(s[j], wtc[i * Cc + j], x);
            s[i] = 1.0f / (1.0f + __expf(-x));
            my[i] = s[i];
        }
    }
    __syncthreads();

    // ---- combine fwd + reversed rev, coalesced store ----
    #pragma unroll
    for (int it = 0; it < (RB * Cc) / THREADS; ++it) {   // 20
        const int idx = tid + it * THREADS;
        const int r = idx / Cc, c = idx - r * Cc;
        const float vf = bases[r * BROW + c];
        const float vr = bases[r * BROW + Cc + (Cc - 1 - c)];
        out[(size_t)(row0 + r) * Cc + c] = 0.5f * (vf + vr);
    }
}

extern "C" void kernel_launch(void* const* d_in, const int* in_sizes, int n_in,
                              void* d_out, int out_size) {
    const float* src = (const float*)d_in[0];
    // d_in[1] = attn_mask (unused)
    const float* W   = (const float*)d_in[2];
    const float* b   = (const float*)d_in[3];
    const float* Wr  = (const float*)d_in[4];
    const float* br  = (const float*)d_in[5];
    float* out = (float*)d_out;

    cudaFuncSetAttribute(bichain_mma5,
                         cudaFuncAttributeMaxDynamicSharedMemorySize, SMEM_BYTES);
    bichain_mma5<<<Bsz / RB, THREADS, SMEM_BYTES>>>(src, W, b, Wr, br, out);
}

// round 6
// speedup vs baseline: 1.3404x; 1.3404x over previous
#include <cuda_runtime.h>
#include <cstdint>

#define Bsz     32768
#define Dd      1024
#define Cc      40
#define CT      80            // 40 fwd + 40 rev output columns
#define RB      128           // rows (M) per CTA -> 256 CTAs
#define THREADS 256           // 8 warps: 4 M-warps x 2 N-warps, each 2 m-tiles x 5 n-tiles
#define KC      32            // k per chunk
#define NCH     (Dd / KC)     // 32
#define NSTAGE  3
#define PADK    40            // floats/row: LDS.64 bank-pair (20r+qc)%16 distinct per half-warp

#define A_FLOATS   (RB * PADK)            // 5120
#define B_FLOATS   (CT * PADK)            // 3200
#define STAGE_F    (A_FLOATS + B_FLOATS)  // 8320 floats = 33280 B
#define OFF0_F     256
#define SMEM_BYTES ((OFF0_F + NSTAGE * STAGE_F) * 4)   // 100864 B -> 2 CTAs/SM

// epilogue overlay (aliases stage buffers after mainloop)
#define BROW    81
#define EPI_BASE_F  OFF0_F
#define EPI_WT_F    (EPI_BASE_F + RB * BROW)          // 256 + 10368
#define EPI_BB_F    (EPI_WT_F + 2 * Cc * Cc)

extern __shared__ float smf[];

// pack two fp32 -> f16x2 (lo in low half): PTX first source fills HIGH half
__device__ __forceinline__ uint32_t pk(float lo, float hi) {
    uint32_t r;
    asm("cvt.rn.f16x2.f32 %0, %1, %2;" : "=r"(r) : "f"(hi), "f"(lo));
    return r;
}

__device__ __forceinline__ void mma_16x8x16(float* d, const uint32_t* a,
                                            const uint32_t* bf) {
    asm volatile(
        "mma.sync.aligned.m16n8k16.row.col.f32.f16.f16.f32 "
        "{%0,%1,%2,%3}, {%4,%5,%6,%7}, {%8,%9}, {%0,%1,%2,%3};"
        : "+f"(d[0]), "+f"(d[1]), "+f"(d[2]), "+f"(d[3])
        : "r"(a[0]), "r"(a[1]), "r"(a[2]), "r"(a[3]), "r"(bf[0]), "r"(bf[1]));
}

__global__ void __launch_bounds__(THREADS, 2)
bichain_h16(const float* __restrict__ src,
            const float* __restrict__ W,  const float* __restrict__ b,
            const float* __restrict__ Wr, const float* __restrict__ br,
            float* __restrict__ out) {
    const int tid  = threadIdx.x;
    const int warp = tid >> 5;
    const int lane = tid & 31;
    const int row0 = blockIdx.x * RB;

    uint32_t smb;
    asm("{ .reg .u64 t; cvta.to.shared.u64 t, %1; cvt.u32.u64 %0, t; }"
        : "=r"(smb) : "l"(smf));

    // ---- cp.async one k-chunk (A 128x32f, B 80x32f), 16B copies ----
    auto issue = [&](int ch) {
        const int st = ch % NSTAGE;
        const int k0 = ch * KC;
        const uint32_t sA = smb + (OFF0_F + st * STAGE_F) * 4;
        const uint32_t sB = sA + A_FLOATS * 4;
        #pragma unroll
        for (int i = 0; i < 4; ++i) {                 // A: 128 rows x 8 segs
            int idx = tid + i * THREADS;
            int r = idx >> 3, seg = idx & 7;
            const float* g = src + (size_t)(row0 + r) * Dd + k0 + seg * 4;
            uint32_t d = sA + (uint32_t)(r * PADK + seg * 4) * 4u;
            asm volatile("cp.async.cg.shared.global [%0], [%1], 16;" :: "r"(d), "l"(g));
        }
        #pragma unroll
        for (int i = 0; i < 3; ++i) {                 // B: 80 rows x 8 segs
            int idx = tid + i * THREADS;
            if (idx < CT * 8) {
                int r = idx >> 3, seg = idx & 7;
                const float* g = (r < Cc ? W  + (size_t)r        * (Dd + Cc)
                                         : Wr + (size_t)(r - Cc) * (Dd + Cc))
                                 + k0 + seg * 4;
                uint32_t d = sB + (uint32_t)(r * PADK + seg * 4) * 4u;
                asm volatile("cp.async.ca.shared.global [%0], [%1], 16;" :: "r"(d), "l"(g));
            }
        }
        asm volatile("cp.async.commit_group;");
    };

    // warp tiling: 4 M-warps (32 rows each) x 2 N-warps (40 cols each)
    const int mw = warp >> 1;          // 0..3
    const int nw = warp & 1;           // 0..1
    const int qr = lane >> 2;          // 0..7
    const int qc = lane & 3;           // 0..3

    // float2-unit base offsets (row*PADK/2 + qc)
    int rA2[2][2], rB2[5];
    #pragma unroll
    for (int mt = 0; mt < 2; ++mt) {
        const int r = mw * 32 + mt * 16 + qr;
        rA2[mt][0] = r * (PADK / 2) + qc;
        rA2[mt][1] = (r + 8) * (PADK / 2) + qc;
    }
    #pragma unroll
    for (int t = 0; t < 5; ++t)
        rB2[t] = (nw * 40 + t * 8 + qr) * (PADK / 2) + qc;

    float acc[2][5][4];
    #pragma unroll
    for (int mt = 0; mt < 2; ++mt)
        #pragma unroll
        for (int t = 0; t < 5; ++t)
            #pragma unroll
            for (int e = 0; e < 4; ++e) acc[mt][t][e] = 0.f;

    issue(0); issue(1);

    for (int ch = 0; ch < NCH; ++ch) {
        if (ch < NCH - 1) asm volatile("cp.async.wait_group 1;");
        else              asm volatile("cp.async.wait_group 0;");
        __syncthreads();
        if (ch + 2 < NCH) issue(ch + 2);              // writes stage (ch-1)%3: safe

        const float2* Ap2 = (const float2*)(smf + OFF0_F + (ch % NSTAGE) * STAGE_F);
        const float2* Bp2 = (const float2*)((const float*)Ap2 + A_FLOATS);

        #pragma unroll
        for (int kk = 0; kk < 2; ++kk) {              // two k16 steps per chunk
            const int kb2 = kk * 8;                   // float2 offset of k-group
            uint32_t afr[2][4], bfr[5][2];
            #pragma unroll
            for (int mt = 0; mt < 2; ++mt) {
                float2 p0 = Ap2[rA2[mt][0] + kb2];
                float2 p1 = Ap2[rA2[mt][1] + kb2];
                float2 p2 = Ap2[rA2[mt][0] + kb2 + 4];
                float2 p3 = Ap2[rA2[mt][1] + kb2 + 4];
                afr[mt][0] = pk(p0.x, p0.y);
                afr[mt][1] = pk(p1.x, p1.y);
                afr[mt][2] = pk(p2.x, p2.y);
                afr[mt][3] = pk(p3.x, p3.y);
            }
            #pragma unroll
            for (int t = 0; t < 5; ++t) {
                float2 q0 = Bp2[rB2[t] + kb2];
                float2 q1 = Bp2[rB2[t] + kb2 + 4];
                bfr[t][0] = pk(q0.x, q0.y);
                bfr[t][1] = pk(q1.x, q1.y);
            }
            #pragma unroll
            for (int mt = 0; mt < 2; ++mt)
                #pragma unroll
                for (int t = 0; t < 5; ++t)
                    mma_16x8x16(acc[mt][t], afr[mt], bfr[t]);
        }
    }
    __syncthreads();   // all warps done with stages before overlay writes

    // ---- accumulators -> smem bases[128][81] ----
    float* bases = smf + EPI_BASE_F;
    #pragma unroll
    for (int mt = 0; mt < 2; ++mt) {
        const int r = mw * 32 + mt * 16 + qr;
        #pragma unroll
        for (int t = 0; t < 5; ++t) {
            const int c = nw * 40 + t * 8 + qc * 2;
            bases[(r    ) * BROW + c    ] = acc[mt][t][0];
            bases[(r    ) * BROW + c + 1] = acc[mt][t][1];
            bases[(r + 8) * BROW + c    ] = acc[mt][t][2];
            bases[(r + 8) * BROW + c + 1] = acc[mt][t][3];
        }
    }

    // chain tail weights W[:,1024:1064] + biases
    float* wt = smf + EPI_WT_F;
    float* bb = smf + EPI_BB_F;
    for (int idx = tid; idx < 2 * Cc * Cc; idx += THREADS) {
        const int chn = idx / (Cc * Cc);
        const int rem = idx - chn * Cc * Cc;
        const int i = rem / Cc, j = rem % Cc;
        const float* Wp = chn ? Wr : W;
        wt[idx] = Wp[(size_t)i * (Dd + Cc) + Dd + j];
    }
    if (tid < 2 * Cc) bb[tid] = (tid < Cc) ? b[tid] : br[tid - Cc];
    __syncthreads();

    // ---- sequential chains: 256 threads = 128 rows x 2 chains ----
    {
        const int row = tid >> 1, chn = tid & 1;
        float* my        = bases + row * BROW + chn * Cc;
        const float* wtc = wt + chn * Cc * Cc;
        const float* bbc = bb + chn * Cc;
        float s[Cc];
        #pragma unroll
        for (int i = 0; i < Cc; ++i) {
            float x = my[i] + bbc[i];
            #pragma unroll
            for (int j = 0; j < i; ++j)
                x = fmaf(s[j], wtc[i * Cc + j], x);
            s[i] = 1.0f / (1.0f + __expf(-x));
            my[i] = s[i];
        }
    }
    __syncthreads();

    // ---- combine fwd + reversed rev, coalesced store ----
    #pragma unroll
    for (int it = 0; it < (RB * Cc) / THREADS; ++it) {   // 20
        const int idx = tid + it * THREADS;
        const int r = idx / Cc, c = idx - r * Cc;
        const float vf = bases[r * BROW + c];
        const float vr = bases[r * BROW + Cc + (Cc - 1 - c)];
        out[(size_t)(row0 + r) * Cc + c] = 0.5f * (vf + vr);
    }
}

extern "C" void kernel_launch(void* const* d_in, const int* in_sizes, int n_in,
                              void* d_out, int out_size) {
    const float* src = (const float*)d_in[0];
    // d_in[1] = attn_mask (unused)
    const float* W   = (const float*)d_in[2];
    const float* b   = (const float*)d_in[3];
    const float* Wr  = (const float*)d_in[4];
    const float* br  = (const float*)d_in[5];
    float* out = (float*)d_out;

    cudaFuncSetAttribute(bichain_h16,
                         cudaFuncAttributeMaxDynamicSharedMemorySize, SMEM_BYTES);
    bichain_h16<<<Bsz / RB, THREADS, SMEM_BYTES>>>(src, W, b, Wr, br, out);
}